// round 14
// baseline (speedup 1.0000x reference)
#include <cuda_runtime.h>
#include <cstdint>

#define T_STEPS 128
#define B_TOT   8192
#define H_DIM   256
#define BETA    0.9f
#define NDIR    32
#define TILE_B  16
#define WIN0    118
#define NWIN    (T_STEPS - WIN0)   // 10
#define MARGIN  1.002f

typedef unsigned long long u64;

__device__ const float c_cs[NDIR] = {
     1.0f,         0.98078528f,  0.92387953f,  0.83146961f,
     0.70710678f,  0.55557023f,  0.38268343f,  0.19509032f,
     0.0f,        -0.19509032f, -0.38268343f, -0.55557023f,
    -0.70710678f, -0.83146961f, -0.92387953f, -0.98078528f,
    -1.0f,        -0.98078528f, -0.92387953f, -0.83146961f,
    -0.70710678f, -0.55557023f, -0.38268343f, -0.19509032f,
     0.0f,         0.19509032f,  0.38268343f,  0.55557023f,
     0.70710678f,  0.83146961f,  0.92387953f,  0.98078528f };
__device__ const float c_sn[NDIR] = {
     0.0f,         0.19509032f,  0.38268343f,  0.55557023f,
     0.70710678f,  0.83146961f,  0.92387953f,  0.98078528f,
     1.0f,         0.98078528f,  0.92387953f,  0.83146961f,
     0.70710678f,  0.55557023f,  0.38268343f,  0.19509032f,
     0.0f,        -0.19509032f, -0.38268343f, -0.55557023f,
    -0.70710678f, -0.83146961f, -0.92387953f, -0.98078528f,
    -1.0f,        -0.98078528f, -0.92387953f, -0.83146961f,
    -0.70710678f, -0.55557023f, -0.38268343f, -0.19509032f };
// beta^(8m), m = 0..15
__device__ const float c_pow8[16] = {
    1.0f, 0.43046721f, 0.18530202f, 0.079766443f,
    0.034336838f, 0.014780883f, 0.0063626854f, 0.0027389442f,
    0.0011790185f, 0.00050752909f, 0.00021847450f, 9.4046100e-05f,
    4.0483775e-05f, 1.7426963e-05f, 7.5018138e-06f, 3.2295300e-06f };

// ---- packed f32x2 helpers ----
__device__ __forceinline__ u64 pk2(float lo, float hi) {
    u64 r; asm("mov.b64 %0, {%1, %2};" : "=l"(r) : "f"(lo), "f"(hi)); return r;
}
__device__ __forceinline__ void unpk2(u64 v, float& lo, float& hi) {
    asm("mov.b64 {%0, %1}, %2;" : "=f"(lo), "=f"(hi) : "l"(v));
}
__device__ __forceinline__ u64 fma2(u64 a, u64 b, u64 c) {
    u64 d; asm("fma.rn.f32x2 %0, %1, %2, %3;" : "=l"(d) : "l"(a), "l"(b), "l"(c)); return d;
}
__device__ __forceinline__ u64 mul2(u64 a, u64 b) {
    u64 d; asm("mul.rn.f32x2 %0, %1, %2;" : "=l"(d) : "l"(a), "l"(b)); return d;
}
__device__ __forceinline__ u64 add2(u64 a, u64 b) {
    u64 d; asm("add.rn.f32x2 %0, %1, %2;" : "=l"(d) : "l"(a), "l"(b)); return d;
}
__device__ __forceinline__ u64 gt1_2(u64 m) {
    u64 r;
    asm("{\n\t"
        ".reg .f32 plo, phi, rl, rh;\n\t"
        "mov.b64 {plo, phi}, %1;\n\t"
        "set.gt.f32.f32 rl, plo, 0f3F800000;\n\t"
        "set.gt.f32.f32 rh, phi, 0f3F800000;\n\t"
        "mov.b64 %0, {rl, rh};\n\t"
        "}" : "=l"(r) : "l"(m));
    return r;
}

// SINGLE kernel. Per-h precompute is done redundantly per block (cheap) and
// overlaps phase A's DRAM latency. Filter: mem_t <= L_t = w.v_t; only spikes
// at t in [118,127] matter; sector-interpolated support bound certifies zeros.
__global__ void __launch_bounds__(256)
snn_mega(const float2* __restrict__ x2,   // [T, B] pairs (x0, x1)
         const float2* __restrict__ w1p,  // [H] pairs
         const float*  __restrict__ w2,   // [2, 256]
         float* __restrict__ out)         // [B, 2]
{
    __shared__ float2 sx[T_STEPS][TILE_B];           // 16KB raw x
    __shared__ unsigned short spool[TILE_B * H_DIM]; // 8KB worst case
    __shared__ float2 sw1[H_DIM];                    // 2KB
    __shared__ float  sw20[H_DIM], sw21[H_DIM];      // 2KB
    __shared__ float  sCa[H_DIM], sCb[H_DIM];        // 2KB
    __shared__ int    sSec[H_DIM];                   // 1KB
    __shared__ float  sD[TILE_B][NDIR];              // 2KB
    __shared__ float2 sEnd[16][TILE_B];              // 2KB
    __shared__ float2 sVw[NWIN][TILE_B];             // 1.25KB
    __shared__ int    sCnt[TILE_B], sOff[TILE_B + 1];
    __shared__ float  sAcc[TILE_B][2];

    const int tid  = threadIdx.x;
    const int lane = tid & 31, wrp = tid >> 5;
    const int b0   = blockIdx.x * TILE_B;

    // ---- phase A (issue first): x tile LDGs into locals (front-batched) ----
    float2 xr[8];
    #pragma unroll
    for (int i = 0; i < 8; ++i) {
        int idx = tid + i * 256;
        xr[i] = x2[(size_t)(idx >> 4) * B_TOT + b0 + (idx & 15)];
    }

    // ---- per-h precompute (independent of x: overlaps the LDG latency) ----
    {
        float2 w = w1p[tid];
        float R  = sqrtf(fmaf(w.x, w.x, w.y * w.y));
        float th = atan2f(w.y, w.x);
        int k  = ((int)floorf(th * 5.092958178940651f) + 64) & 31;   // 16/pi
        int k1 = (k + 1) & 31;
        const float inv_det = 1.0f / 0.19509032201612825f;           // 1/sin(pi/16)
        float iR = 1.0f / fmaxf(R, 1e-30f);
        float nx = w.x * iR, ny = w.y * iR;
        float a = (nx * c_sn[k1] - ny * c_cs[k1]) * inv_det;
        float b = (ny * c_cs[k]  - nx * c_sn[k])  * inv_det;
        sw1[tid]  = w;
        sCa[tid]  = fmaxf(a, 0.f) * R * MARGIN;
        sCb[tid]  = fmaxf(b, 0.f) * R * MARGIN;
        sSec[tid] = k;
        sw20[tid] = w2[tid];
        sw21[tid] = w2[H_DIM + tid];
    }
    if (tid < TILE_B * 2) ((float*)sAcc)[tid] = 0.f;

    // store x tile
    #pragma unroll
    for (int i = 0; i < 8; ++i) {
        int idx = tid + i * 256;
        sx[idx >> 4][idx & 15] = xr[i];
    }
    __syncthreads();

    // ---- phase B1: segmented scan local sums (thread = (segment j, bl)) ----
    {
        const int j = tid >> 4, bl = tid & 15;
        float A = 0.f, Bv = 0.f;
        #pragma unroll
        for (int i = 0; i < 8; ++i) {
            float2 xv = sx[8 * j + i][bl];
            A  = fmaf(A,  BETA, xv.x);
            Bv = fmaf(Bv, BETA, xv.y);
        }
        sEnd[j][bl] = make_float2(A, Bv);
    }
    __syncthreads();

    // ---- phase B2: window segments reconstruct v_t, t in [118,128) ----
    {
        const int j = tid >> 4, bl = tid & 15;
        if (j >= 14) {
            float VA = 0.f, VB = 0.f;                 // v_{8j-1}
            for (int i = 0; i < j; ++i) {
                float2 e = sEnd[i][bl];
                float p = c_pow8[j - 1 - i];
                VA = fmaf(e.x, p, VA);
                VB = fmaf(e.y, p, VB);
            }
            #pragma unroll
            for (int i = 0; i < 8; ++i) {
                float2 xv = sx[8 * j + i][bl];
                VA = fmaf(VA, BETA, xv.x);
                VB = fmaf(VB, BETA, xv.y);
                int t = 8 * j + i;
                if (t >= WIN0) sVw[t - WIN0][bl] = make_float2(VA, VB);
            }
        }
    }
    __syncthreads();

    // ---- phase B3: directional window support (2 tasks/thread) ----
    {
        const int k = tid & 31;
        const int bl0 = tid >> 5, bl1 = bl0 + 8;
        const float cs = c_cs[k], sn = c_sn[k];
        float D0 = -1e30f, D1 = -1e30f;
        #pragma unroll
        for (int i = 0; i < NWIN; ++i) {
            float2 v0 = sVw[i][bl0];
            float2 v1 = sVw[i][bl1];
            D0 = fmaxf(D0, fmaf(v0.x, cs, v0.y * sn));
            D1 = fmaxf(D1, fmaf(v1.x, cs, v1.y * sn));
        }
        sD[bl0][k] = D0;
        sD[bl1][k] = D1;
    }
    __syncthreads();

    // ---- phase C1: survivor counts (warp w -> bl = w, w+8) ----
    unsigned predbits[2] = {0u, 0u};
    #pragma unroll
    for (int r = 0; r < 2; ++r) {
        const int bl = wrp + r * 8;
        int cnt = 0;
        #pragma unroll
        for (int c = 0; c < 8; ++c) {
            const int h = c * 32 + lane;
            const int k = sSec[h];
            float bound = sCa[h] * sD[bl][k] + sCb[h] * sD[bl][(k + 1) & 31];
            bool pred = (bound >= 0.999f);
            if (pred) predbits[r] |= (1u << c);
            cnt += __popc(__ballot_sync(0xffffffffu, pred));
        }
        if (lane == 0) sCnt[bl] = cnt;
    }
    __syncthreads();
    if (tid == 0) {
        int s = 0;
        #pragma unroll
        for (int i = 0; i < TILE_B; ++i) { sOff[i] = s; s += sCnt[i]; }
        sOff[TILE_B] = s;
    }
    __syncthreads();

    // ---- phase C2: deterministic scatter into block-local pool ----
    #pragma unroll
    for (int r = 0; r < 2; ++r) {
        const int bl = wrp + r * 8;
        int base = sOff[bl];
        #pragma unroll
        for (int c = 0; c < 8; ++c) {
            bool pred = (predbits[r] >> c) & 1u;
            unsigned mask = __ballot_sync(0xffffffffu, pred);
            if (pred) {
                int pos = base + __popc(mask & ((1u << lane) - 1u));
                spool[pos] = (unsigned short)((bl << 8) | (c * 32 + lane));
            }
            base += __popc(mask);
        }
    }
    __syncthreads();

    // ---- phase D: pooled exact LIF scan, 128 survivors per warp-pass
    //      (4 per lane = 2 independent packed chains -> latency hiding) ----
    const int M = sOff[TILE_B];
    const u64 BETA2 = 0x3F6666663F666666ULL;
    const u64 NEG12 = 0xBF800000BF800000ULL;

    for (int s0 = wrp * 128; s0 < M; s0 += 8 * 128) {
        const int ia = s0 + lane,      ib = s0 + 32 + lane;
        const int ic = s0 + 64 + lane, id = s0 + 96 + lane;
        const bool acta = ia < M, actb = ib < M, actc = ic < M, actd = id < M;
        const unsigned ea = spool[acta ? ia : 0];
        const unsigned eb = spool[actb ? ib : 0];
        const unsigned ec = spool[actc ? ic : 0];
        const unsigned ed = spool[actd ? id : 0];
        const int bla = ea >> 8, ha = ea & 255;
        const int blb = eb >> 8, hb = eb & 255;
        const int blc = ec >> 8, hc = ec & 255;
        const int bld = ed >> 8, hd = ed & 255;
        const float2 wa = sw1[ha], wb = sw1[hb], wc = sw1[hc], wd = sw1[hd];
        const u64 w0p0 = pk2(wa.x, wb.x), w1q0 = pk2(wa.y, wb.y);
        const u64 w0p1 = pk2(wc.x, wd.x), w1q1 = pk2(wc.y, wd.y);

        u64 m0 = 0, m1 = 0, cnt0 = 0, cnt1 = 0;
        #pragma unroll 2
        for (int t = 0; t < WIN0; ++t) {
            float2 xa = sx[t][bla], xb = sx[t][blb];
            float2 xc = sx[t][blc], xd = sx[t][bld];
            u64 qx0 = pk2(xa.x, xb.x), qy0 = pk2(xa.y, xb.y);
            u64 qx1 = pk2(xc.x, xd.x), qy1 = pk2(xc.y, xd.y);
            u64 s0v = gt1_2(m0);
            u64 s1v = gt1_2(m1);
            m0 = fma2(m0, BETA2, fma2(qx0, w0p0, mul2(qy0, w1q0)));
            m1 = fma2(m1, BETA2, fma2(qx1, w0p1, mul2(qy1, w1q1)));
            m0 = fma2(s0v, NEG12, m0);
            m1 = fma2(s1v, NEG12, m1);
        }
        #pragma unroll
        for (int t = WIN0; t < T_STEPS; ++t) {
            float2 xa = sx[t][bla], xb = sx[t][blb];
            float2 xc = sx[t][blc], xd = sx[t][bld];
            u64 qx0 = pk2(xa.x, xb.x), qy0 = pk2(xa.y, xb.y);
            u64 qx1 = pk2(xc.x, xd.x), qy1 = pk2(xc.y, xd.y);
            u64 s0v = gt1_2(m0);
            u64 s1v = gt1_2(m1);
            m0 = fma2(m0, BETA2, fma2(qx0, w0p0, mul2(qy0, w1q0)));
            m1 = fma2(m1, BETA2, fma2(qx1, w0p1, mul2(qy1, w1q1)));
            m0 = fma2(s0v, NEG12, m0);
            m1 = fma2(s1v, NEG12, m1);
            cnt0 = add2(cnt0, gt1_2(m0));
            cnt1 = add2(cnt1, gt1_2(m1));
        }

        float ca, cb, cc, cd;
        unpk2(cnt0, ca, cb);
        unpk2(cnt1, cc, cd);
        if (acta && ca != 0.f) {
            atomicAdd(&sAcc[bla][0], ca * sw20[ha]);
            atomicAdd(&sAcc[bla][1], ca * sw21[ha]);
        }
        if (actb && cb != 0.f) {
            atomicAdd(&sAcc[blb][0], cb * sw20[hb]);
            atomicAdd(&sAcc[blb][1], cb * sw21[hb]);
        }
        if (actc && cc != 0.f) {
            atomicAdd(&sAcc[blc][0], cc * sw20[hc]);
            atomicAdd(&sAcc[blc][1], cc * sw21[hc]);
        }
        if (actd && cd != 0.f) {
            atomicAdd(&sAcc[bld][0], cd * sw20[hd]);
            atomicAdd(&sAcc[bld][1], cd * sw21[hd]);
        }
    }
    __syncthreads();

    // ---- output: exclusive plain stores ----
    if (tid < TILE_B * 2) {
        int bl = tid >> 1, o = tid & 1;
        out[(b0 + bl) * 2 + o] = 0.1f * sAcc[bl][o];
    }
}

extern "C" void kernel_launch(void* const* d_in, const int* in_sizes, int n_in,
                              void* d_out, int out_size) {
    const float2* x  = (const float2*)d_in[0];   // [128, 8192, 2] f32
    const float2* W1 = (const float2*)d_in[1];   // [256, 2] f32
    const float*  W2 = (const float*)d_in[2];    // [2, 256] f32
    float* out = (float*)d_out;                  // [8192, 2] f32

    snn_mega<<<B_TOT / TILE_B, 256>>>(x, W1, W2, out);
}

// round 15
// speedup vs baseline: 1.1119x; 1.1119x over previous
#include <cuda_runtime.h>
#include <cstdint>

#define T_STEPS 128
#define B_TOT   8192
#define H_DIM   256
#define BETA    0.9f
#define TILE_B  16
#define WIN0    118
#define NWIN    (T_STEPS - WIN0)   // 10
#define TH_LO   0.999f             // abs margin >> fp error of the scan path

typedef unsigned long long u64;

// beta^(8m), m = 0..15
__device__ const float c_pow8[16] = {
    1.0f, 0.43046721f, 0.18530202f, 0.079766443f,
    0.034336838f, 0.014780883f, 0.0063626854f, 0.0027389442f,
    0.0011790185f, 0.00050752909f, 0.00021847450f, 9.4046100e-05f,
    4.0483775e-05f, 1.7426963e-05f, 7.5018138e-06f, 3.2295300e-06f };

// ---- packed f32x2 helpers ----
__device__ __forceinline__ u64 pk2(float lo, float hi) {
    u64 r; asm("mov.b64 %0, {%1, %2};" : "=l"(r) : "f"(lo), "f"(hi)); return r;
}
__device__ __forceinline__ void unpk2(u64 v, float& lo, float& hi) {
    asm("mov.b64 {%0, %1}, %2;" : "=f"(lo), "=f"(hi) : "l"(v));
}
__device__ __forceinline__ u64 fma2(u64 a, u64 b, u64 c) {
    u64 d; asm("fma.rn.f32x2 %0, %1, %2, %3;" : "=l"(d) : "l"(a), "l"(b), "l"(c)); return d;
}
__device__ __forceinline__ u64 mul2(u64 a, u64 b) {
    u64 d; asm("mul.rn.f32x2 %0, %1, %2;" : "=l"(d) : "l"(a), "l"(b)); return d;
}
__device__ __forceinline__ u64 add2(u64 a, u64 b) {
    u64 d; asm("add.rn.f32x2 %0, %1, %2;" : "=l"(d) : "l"(a), "l"(b)); return d;
}
__device__ __forceinline__ u64 gt1_2(u64 m) {
    u64 r;
    asm("{\n\t"
        ".reg .f32 plo, phi, rl, rh;\n\t"
        "mov.b64 {plo, phi}, %1;\n\t"
        "set.gt.f32.f32 rl, plo, 0f3F800000;\n\t"
        "set.gt.f32.f32 rh, phi, 0f3F800000;\n\t"
        "mov.b64 %0, {rl, rh};\n\t"
        "}" : "=l"(r) : "l"(m));
    return r;
}

// SINGLE kernel. Filter uses the EXACT linear window max:
//   mem_t <= L_t = w.v_t (resets only subtract), and only t in [118,127]
//   matters, so if max_i w.v_i < 1 the neuron contributes exactly 0.
// The 10 window v's are materialized by a segmented scan, so the exact
// max is 10 FFMA + 10 FMAX per (b,h) -- no atan2/sector machinery at all.
__global__ void __launch_bounds__(256)
snn_mega(const float2* __restrict__ x2,   // [T, B] pairs (x0, x1)
         const float2* __restrict__ w1p,  // [H] pairs
         const float*  __restrict__ w2,   // [2, 256]
         float* __restrict__ out)         // [B, 2]
{
    __shared__ float2 sx[T_STEPS][TILE_B];           // 16KB raw x
    __shared__ unsigned short spool[TILE_B * H_DIM]; // 8KB worst case
    __shared__ float2 sw1[H_DIM];                    // 2KB
    __shared__ float  sw20[H_DIM], sw21[H_DIM];      // 2KB
    __shared__ float2 sEnd[16][TILE_B];              // 2KB segment end sums
    __shared__ float2 sVw[NWIN][TILE_B];             // 1.25KB window v values
    __shared__ int    sCnt[TILE_B], sOff[TILE_B + 1];
    __shared__ float  sAcc[TILE_B][2];

    const int tid  = threadIdx.x;
    const int lane = tid & 31, wrp = tid >> 5;
    const int b0   = blockIdx.x * TILE_B;

    // ---- tables (cheap: plain loads only) ----
    sw1[tid]  = w1p[tid];
    sw20[tid] = w2[tid];
    sw21[tid] = w2[H_DIM + tid];
    if (tid < TILE_B * 2) ((float*)sAcc)[tid] = 0.f;

    // ---- phase A: stage x (coalesced per t-row) ----
    #pragma unroll
    for (int i = 0; i < 8; ++i) {
        int idx = tid + i * 256;
        int t = idx >> 4, bl = idx & 15;
        sx[t][bl] = x2[(size_t)t * B_TOT + b0 + bl];
    }
    __syncthreads();

    // ---- phase B1: segmented scan local sums (thread = (segment j, bl)) ----
    {
        const int j = tid >> 4, bl = tid & 15;
        float A = 0.f, Bv = 0.f;
        #pragma unroll
        for (int i = 0; i < 8; ++i) {
            float2 xv = sx[8 * j + i][bl];
            A  = fmaf(A,  BETA, xv.x);
            Bv = fmaf(Bv, BETA, xv.y);
        }
        sEnd[j][bl] = make_float2(A, Bv);
    }
    __syncthreads();

    // ---- phase B2: window segments reconstruct v_t, t in [118,128) ----
    {
        const int j = tid >> 4, bl = tid & 15;
        if (j >= 14) {
            float VA = 0.f, VB = 0.f;                 // v_{8j-1}
            for (int i = 0; i < j; ++i) {
                float2 e = sEnd[i][bl];
                float p = c_pow8[j - 1 - i];
                VA = fmaf(e.x, p, VA);
                VB = fmaf(e.y, p, VB);
            }
            #pragma unroll
            for (int i = 0; i < 8; ++i) {
                float2 xv = sx[8 * j + i][bl];
                VA = fmaf(VA, BETA, xv.x);
                VB = fmaf(VB, BETA, xv.y);
                int t = 8 * j + i;
                if (t >= WIN0) sVw[t - WIN0][bl] = make_float2(VA, VB);
            }
        }
    }
    __syncthreads();

    // ---- phase C1: EXACT window-max filter (warp w -> bl = w, w+8) ----
    unsigned predbits[2] = {0u, 0u};
    #pragma unroll
    for (int r = 0; r < 2; ++r) {
        const int bl = wrp + r * 8;
        float2 vv[NWIN];
        #pragma unroll
        for (int i = 0; i < NWIN; ++i) vv[i] = sVw[i][bl];   // warp-uniform
        int cnt = 0;
        #pragma unroll
        for (int c = 0; c < 8; ++c) {
            const int h = c * 32 + lane;
            const float2 w = sw1[h];
            float bmax = -1e30f;
            #pragma unroll
            for (int i = 0; i < NWIN; ++i)
                bmax = fmaxf(bmax, fmaf(vv[i].x, w.x, vv[i].y * w.y));
            bool pred = (bmax >= TH_LO);              // may spike in window
            if (pred) predbits[r] |= (1u << c);
            cnt += __popc(__ballot_sync(0xffffffffu, pred));
        }
        if (lane == 0) sCnt[bl] = cnt;
    }
    __syncthreads();
    if (tid == 0) {
        int s = 0;
        #pragma unroll
        for (int i = 0; i < TILE_B; ++i) { sOff[i] = s; s += sCnt[i]; }
        sOff[TILE_B] = s;
    }
    __syncthreads();

    // ---- phase C2: deterministic scatter into block-local pool ----
    #pragma unroll
    for (int r = 0; r < 2; ++r) {
        const int bl = wrp + r * 8;
        int base = sOff[bl];
        #pragma unroll
        for (int c = 0; c < 8; ++c) {
            bool pred = (predbits[r] >> c) & 1u;
            unsigned mask = __ballot_sync(0xffffffffu, pred);
            if (pred) {
                int pos = base + __popc(mask & ((1u << lane) - 1u));
                spool[pos] = (unsigned short)((bl << 8) | (c * 32 + lane));
            }
            base += __popc(mask);
        }
    }
    __syncthreads();

    // ---- phase D: pooled exact LIF scan (64 entries per warp-pass) ----
    const int M = sOff[TILE_B];
    const u64 BETA2 = 0x3F6666663F666666ULL;
    const u64 NEG12 = 0xBF800000BF800000ULL;

    for (int s0 = wrp * 64; s0 < M; s0 += 8 * 64) {
        const int ia = s0 + lane, ib = s0 + 32 + lane;
        const bool acta = ia < M, actb = ib < M;
        const unsigned ea = spool[acta ? ia : 0];
        const unsigned eb = spool[actb ? ib : 0];
        const int bla = ea >> 8, ha = ea & 255;
        const int blb = eb >> 8, hb = eb & 255;
        const float2 wa = sw1[ha], wb = sw1[hb];
        const u64 w0p = pk2(wa.x, wb.x);
        const u64 w1q = pk2(wa.y, wb.y);

        u64 m = 0, cnt = 0;
        #pragma unroll 4
        for (int t = 0; t < WIN0; ++t) {
            float2 xa = sx[t][bla];
            float2 xb = sx[t][blb];
            u64 qx = pk2(xa.x, xb.x);
            u64 qy = pk2(xa.y, xb.y);
            u64 s = gt1_2(m);                       // reset from prev mem
            m = fma2(m, BETA2, fma2(qx, w0p, mul2(qy, w1q)));
            m = fma2(s, NEG12, m);
        }
        #pragma unroll
        for (int t = WIN0; t < T_STEPS; ++t) {
            float2 xa = sx[t][bla];
            float2 xb = sx[t][blb];
            u64 qx = pk2(xa.x, xb.x);
            u64 qy = pk2(xa.y, xb.y);
            u64 s = gt1_2(m);
            m = fma2(m, BETA2, fma2(qx, w0p, mul2(qy, w1q)));
            m = fma2(s, NEG12, m);
            cnt = add2(cnt, gt1_2(m));              // spk_t, t in [118,127]
        }

        float ca, cb;
        unpk2(cnt, ca, cb);
        if (acta && ca != 0.f) {
            atomicAdd(&sAcc[bla][0], ca * sw20[ha]);
            atomicAdd(&sAcc[bla][1], ca * sw21[ha]);
        }
        if (actb && cb != 0.f) {
            atomicAdd(&sAcc[blb][0], cb * sw20[hb]);
            atomicAdd(&sAcc[blb][1], cb * sw21[hb]);
        }
    }
    __syncthreads();

    // ---- output: exclusive plain stores ----
    if (tid < TILE_B * 2) {
        int bl = tid >> 1, o = tid & 1;
        out[(b0 + bl) * 2 + o] = 0.1f * sAcc[bl][o];
    }
}

extern "C" void kernel_launch(void* const* d_in, const int* in_sizes, int n_in,
                              void* d_out, int out_size) {
    const float2* x  = (const float2*)d_in[0];   // [128, 8192, 2] f32
    const float2* W1 = (const float2*)d_in[1];   // [256, 2] f32
    const float*  W2 = (const float*)d_in[2];    // [2, 256] f32
    float* out = (float*)d_out;                  // [8192, 2] f32

    snn_mega<<<B_TOT / TILE_B, 256>>>(x, W1, W2, out);
}

// round 16
// speedup vs baseline: 1.2239x; 1.1007x over previous
#include <cuda_runtime.h>
#include <cstdint>

#define T_STEPS 128
#define B_TOT   8192
#define H_DIM   256
#define BETA    0.9f
#define TILE_B  16
#define WIN0    118
#define NWIN    (T_STEPS - WIN0)   // 10
#define TH_LO   0.999f             // exact-test margin >> fp error
#define TH2_LO  0.997f             // cheap-test margin (superset of exact)

typedef unsigned long long u64;

// beta^(8m), m = 0..15
__device__ const float c_pow8[16] = {
    1.0f, 0.43046721f, 0.18530202f, 0.079766443f,
    0.034336838f, 0.014780883f, 0.0063626854f, 0.0027389442f,
    0.0011790185f, 0.00050752909f, 0.00021847450f, 9.4046100e-05f,
    4.0483775e-05f, 1.7426963e-05f, 7.5018138e-06f, 3.2295300e-06f };

// ---- packed f32x2 helpers ----
__device__ __forceinline__ u64 pk2(float lo, float hi) {
    u64 r; asm("mov.b64 %0, {%1, %2};" : "=l"(r) : "f"(lo), "f"(hi)); return r;
}
__device__ __forceinline__ void unpk2(u64 v, float& lo, float& hi) {
    asm("mov.b64 {%0, %1}, %2;" : "=f"(lo), "=f"(hi) : "l"(v));
}
__device__ __forceinline__ u64 fma2(u64 a, u64 b, u64 c) {
    u64 d; asm("fma.rn.f32x2 %0, %1, %2, %3;" : "=l"(d) : "l"(a), "l"(b), "l"(c)); return d;
}
__device__ __forceinline__ u64 mul2(u64 a, u64 b) {
    u64 d; asm("mul.rn.f32x2 %0, %1, %2;" : "=l"(d) : "l"(a), "l"(b)); return d;
}
__device__ __forceinline__ u64 add2(u64 a, u64 b) {
    u64 d; asm("add.rn.f32x2 %0, %1, %2;" : "=l"(d) : "l"(a), "l"(b)); return d;
}
__device__ __forceinline__ u64 gt1_2(u64 m) {
    u64 r;
    asm("{\n\t"
        ".reg .f32 plo, phi, rl, rh;\n\t"
        "mov.b64 {plo, phi}, %1;\n\t"
        "set.gt.f32.f32 rl, plo, 0f3F800000;\n\t"
        "set.gt.f32.f32 rh, phi, 0f3F800000;\n\t"
        "mov.b64 %0, {rl, rh};\n\t"
        "}" : "=l"(r) : "l"(m));
    return r;
}

// SINGLE kernel. Two-stage filter:
//  C1a cheap:  R^2[h] * Vmax^2[bl] >= TH2_LO   (Cauchy-Schwarz superset)
//  C1b exact:  max_i w.v_i >= TH_LO on compacted candidates only.
// mem_t <= L_t = w.v_t (resets only subtract) and only t in [118,127] matter,
// so failing the exact test certifies a zero contribution.
__global__ void __launch_bounds__(256)
snn_mega(const float2* __restrict__ x2,   // [T, B] pairs (x0, x1)
         const float2* __restrict__ w1p,  // [H] pairs
         const float*  __restrict__ w2,   // [2, 256]
         float* __restrict__ out)         // [B, 2]
{
    __shared__ float2 sx[T_STEPS][TILE_B];            // 16KB raw x
    __shared__ unsigned short pool1[TILE_B * H_DIM];  // 8KB candidates
    __shared__ unsigned short spool[TILE_B * H_DIM];  // 8KB survivors
    __shared__ float2 sw1[H_DIM];                     // 2KB
    __shared__ float  sw20[H_DIM], sw21[H_DIM];       // 2KB
    __shared__ float  sR2[H_DIM];                     // 1KB  |w|^2
    __shared__ float2 sEnd[16][TILE_B];               // 2KB  segment end sums
    __shared__ float2 sVw[NWIN][TILE_B];              // 1.25KB window v values
    __shared__ float  sVmax2[TILE_B];                 // window max |v|^2
    __shared__ int    sCnt[TILE_B], sOff[TILE_B + 1];
    __shared__ int    wCnt[8], wBase[8], sM;
    __shared__ float  sAcc[TILE_B][2];

    const int tid  = threadIdx.x;
    const int lane = tid & 31, wrp = tid >> 5;
    const int b0   = blockIdx.x * TILE_B;

    // ---- tables (plain loads; R^2 instead of sqrt/atan2) ----
    {
        float2 w = w1p[tid];
        sw1[tid]  = w;
        sR2[tid]  = fmaf(w.x, w.x, w.y * w.y);
        sw20[tid] = w2[tid];
        sw21[tid] = w2[H_DIM + tid];
    }
    if (tid < TILE_B * 2) ((float*)sAcc)[tid] = 0.f;

    // ---- phase A: stage x (coalesced per t-row) ----
    #pragma unroll
    for (int i = 0; i < 8; ++i) {
        int idx = tid + i * 256;
        int t = idx >> 4, bl = idx & 15;
        sx[t][bl] = x2[(size_t)t * B_TOT + b0 + bl];
    }
    __syncthreads();

    // ---- phase B1: segmented scan local sums (thread = (segment j, bl)) ----
    {
        const int j = tid >> 4, bl = tid & 15;
        float A = 0.f, Bv = 0.f;
        #pragma unroll
        for (int i = 0; i < 8; ++i) {
            float2 xv = sx[8 * j + i][bl];
            A  = fmaf(A,  BETA, xv.x);
            Bv = fmaf(Bv, BETA, xv.y);
        }
        sEnd[j][bl] = make_float2(A, Bv);
    }
    __syncthreads();

    // ---- phase B2: window segments reconstruct v_t, t in [118,128) ----
    {
        const int j = tid >> 4, bl = tid & 15;
        if (j >= 14) {
            float VA = 0.f, VB = 0.f;                 // v_{8j-1}
            for (int i = 0; i < j; ++i) {
                float2 e = sEnd[i][bl];
                float p = c_pow8[j - 1 - i];
                VA = fmaf(e.x, p, VA);
                VB = fmaf(e.y, p, VB);
            }
            #pragma unroll
            for (int i = 0; i < 8; ++i) {
                float2 xv = sx[8 * j + i][bl];
                VA = fmaf(VA, BETA, xv.x);
                VB = fmaf(VB, BETA, xv.y);
                int t = 8 * j + i;
                if (t >= WIN0) sVw[t - WIN0][bl] = make_float2(VA, VB);
            }
        }
    }
    __syncthreads();

    // ---- window max |v|^2 per bl ----
    if (tid < TILE_B) {
        float vm = 0.f;
        #pragma unroll
        for (int k = 0; k < NWIN; ++k) {
            float2 v = sVw[k][tid];
            vm = fmaxf(vm, fmaf(v.x, v.x, v.y * v.y));
        }
        sVmax2[tid] = vm;
    }
    __syncthreads();

    // ---- phase C1a: CHEAP candidate test (warp w -> bl = w, w+8) ----
    unsigned predbits[2] = {0u, 0u};
    #pragma unroll
    for (int r = 0; r < 2; ++r) {
        const int bl = wrp + r * 8;
        const float vm2 = sVmax2[bl];
        int cnt = 0;
        #pragma unroll
        for (int c = 0; c < 8; ++c) {
            const int h = c * 32 + lane;
            bool pred = (sR2[h] * vm2 >= TH2_LO);
            if (pred) predbits[r] |= (1u << c);
            cnt += __popc(__ballot_sync(0xffffffffu, pred));
        }
        if (lane == 0) sCnt[bl] = cnt;
    }
    __syncthreads();
    if (tid == 0) {
        int s = 0;
        #pragma unroll
        for (int i = 0; i < TILE_B; ++i) { sOff[i] = s; s += sCnt[i]; }
        sOff[TILE_B] = s;
        sM = 0;
    }
    __syncthreads();

    // ---- scatter candidates into pool1 (deterministic) ----
    #pragma unroll
    for (int r = 0; r < 2; ++r) {
        const int bl = wrp + r * 8;
        int base = sOff[bl];
        #pragma unroll
        for (int c = 0; c < 8; ++c) {
            bool pred = (predbits[r] >> c) & 1u;
            unsigned mask = __ballot_sync(0xffffffffu, pred);
            if (pred) {
                int pos = base + __popc(mask & ((1u << lane) - 1u));
                pool1[pos] = (unsigned short)((bl << 8) | (c * 32 + lane));
            }
            base += __popc(mask);
        }
    }
    __syncthreads();

    // ---- phase C1b: EXACT test on candidates only, compact into spool ----
    const int P1 = sOff[TILE_B];
    for (int base = 0; base < P1; base += 256) {
        const int i = base + tid;
        const bool act = i < P1;
        const unsigned e = pool1[act ? i : 0];
        const int bl = e >> 8, h = e & 255;
        const float2 w = sw1[h];
        float bmax = -1e30f;
        #pragma unroll
        for (int k = 0; k < NWIN; ++k) {
            float2 v = sVw[k][bl];
            bmax = fmaxf(bmax, fmaf(v.x, w.x, v.y * w.y));
        }
        bool pred = act && (bmax >= TH_LO);
        unsigned mask = __ballot_sync(0xffffffffu, pred);
        if (lane == 0) wCnt[wrp] = __popc(mask);
        __syncthreads();
        if (tid == 0) {
            int s = sM;
            #pragma unroll
            for (int wv = 0; wv < 8; ++wv) { wBase[wv] = s; s += wCnt[wv]; }
            sM = s;
        }
        __syncthreads();
        if (pred) {
            int pos = wBase[wrp] + __popc(mask & ((1u << lane) - 1u));
            spool[pos] = (unsigned short)e;
        }
        __syncthreads();
    }

    // ---- phase D: pooled exact LIF scan (64 entries per warp-pass) ----
    const int M = sM;
    const u64 BETA2 = 0x3F6666663F666666ULL;
    const u64 NEG12 = 0xBF800000BF800000ULL;

    for (int s0 = wrp * 64; s0 < M; s0 += 8 * 64) {
        const int ia = s0 + lane, ib = s0 + 32 + lane;
        const bool acta = ia < M, actb = ib < M;
        const unsigned ea = spool[acta ? ia : 0];
        const unsigned eb = spool[actb ? ib : 0];
        const int bla = ea >> 8, ha = ea & 255;
        const int blb = eb >> 8, hb = eb & 255;
        const float2 wa = sw1[ha], wb = sw1[hb];
        const u64 w0p = pk2(wa.x, wb.x);
        const u64 w1q = pk2(wa.y, wb.y);

        u64 m = 0, cnt = 0;
        #pragma unroll 4
        for (int t = 0; t < WIN0; ++t) {
            float2 xa = sx[t][bla];
            float2 xb = sx[t][blb];
            u64 qx = pk2(xa.x, xb.x);
            u64 qy = pk2(xa.y, xb.y);
            u64 s = gt1_2(m);                       // reset from prev mem
            m = fma2(m, BETA2, fma2(qx, w0p, mul2(qy, w1q)));
            m = fma2(s, NEG12, m);
        }
        #pragma unroll
        for (int t = WIN0; t < T_STEPS; ++t) {
            float2 xa = sx[t][bla];
            float2 xb = sx[t][blb];
            u64 qx = pk2(xa.x, xb.x);
            u64 qy = pk2(xa.y, xb.y);
            u64 s = gt1_2(m);
            m = fma2(m, BETA2, fma2(qx, w0p, mul2(qy, w1q)));
            m = fma2(s, NEG12, m);
            cnt = add2(cnt, gt1_2(m));              // spk_t, t in [118,127]
        }

        float ca, cb;
        unpk2(cnt, ca, cb);
        if (acta && ca != 0.f) {
            atomicAdd(&sAcc[bla][0], ca * sw20[ha]);
            atomicAdd(&sAcc[bla][1], ca * sw21[ha]);
        }
        if (actb && cb != 0.f) {
            atomicAdd(&sAcc[blb][0], cb * sw20[hb]);
            atomicAdd(&sAcc[blb][1], cb * sw21[hb]);
        }
    }
    __syncthreads();

    // ---- output: exclusive plain stores ----
    if (tid < TILE_B * 2) {
        int bl = tid >> 1, o = tid & 1;
        out[(b0 + bl) * 2 + o] = 0.1f * sAcc[bl][o];
    }
}

extern "C" void kernel_launch(void* const* d_in, const int* in_sizes, int n_in,
                              void* d_out, int out_size) {
    const float2* x  = (const float2*)d_in[0];   // [128, 8192, 2] f32
    const float2* W1 = (const float2*)d_in[1];   // [256, 2] f32
    const float*  W2 = (const float*)d_in[2];    // [2, 256] f32
    float* out = (float*)d_out;                  // [8192, 2] f32

    snn_mega<<<B_TOT / TILE_B, 256>>>(x, W1, W2, out);
}

// round 17
// speedup vs baseline: 1.2448x; 1.0171x over previous
#include <cuda_runtime.h>
#include <cstdint>

#define T_STEPS 128
#define B_TOT   8192
#define H_DIM   256
#define BETA    0.9f
#define TILE_B  16
#define WIN0    118
#define NWIN    (T_STEPS - WIN0)   // 10
#define TH_LO   0.999f             // exact-test margin >> fp error
#define TH2_LO  0.997f             // cheap-test margin (superset of exact)

typedef unsigned long long u64;

// beta^(8m), m = 0..15
__device__ const float c_pow8[16] = {
    1.0f, 0.43046721f, 0.18530202f, 0.079766443f,
    0.034336838f, 0.014780883f, 0.0063626854f, 0.0027389442f,
    0.0011790185f, 0.00050752909f, 0.00021847450f, 9.4046100e-05f,
    4.0483775e-05f, 1.7426963e-05f, 7.5018138e-06f, 3.2295300e-06f };

// ---- packed f32x2 helpers ----
__device__ __forceinline__ u64 pk2(float lo, float hi) {
    u64 r; asm("mov.b64 %0, {%1, %2};" : "=l"(r) : "f"(lo), "f"(hi)); return r;
}
__device__ __forceinline__ void unpk2(u64 v, float& lo, float& hi) {
    asm("mov.b64 {%0, %1}, %2;" : "=f"(lo), "=f"(hi) : "l"(v));
}
__device__ __forceinline__ u64 fma2(u64 a, u64 b, u64 c) {
    u64 d; asm("fma.rn.f32x2 %0, %1, %2, %3;" : "=l"(d) : "l"(a), "l"(b), "l"(c)); return d;
}
__device__ __forceinline__ u64 mul2(u64 a, u64 b) {
    u64 d; asm("mul.rn.f32x2 %0, %1, %2;" : "=l"(d) : "l"(a), "l"(b)); return d;
}
__device__ __forceinline__ u64 add2(u64 a, u64 b) {
    u64 d; asm("add.rn.f32x2 %0, %1, %2;" : "=l"(d) : "l"(a), "l"(b)); return d;
}
__device__ __forceinline__ u64 gt1_2(u64 m) {
    u64 r;
    asm("{\n\t"
        ".reg .f32 plo, phi, rl, rh;\n\t"
        "mov.b64 {plo, phi}, %1;\n\t"
        "set.gt.f32.f32 rl, plo, 0f3F800000;\n\t"
        "set.gt.f32.f32 rh, phi, 0f3F800000;\n\t"
        "mov.b64 %0, {rl, rh};\n\t"
        "}" : "=l"(r) : "l"(m));
    return r;
}

// SINGLE kernel. Two-stage filter with IN-PLACE compaction (one pool):
//  C1a cheap:  R^2[h] >= TH2_LO / Vmax^2[bl]   (Cauchy-Schwarz superset)
//  C1b exact:  max_i w.v_i >= TH_LO, compacted in place within spool.
// mem_t <= L_t = w.v_t (resets only subtract) and only t in [118,127] matter,
// so failing the exact test certifies a zero contribution.
__global__ void __launch_bounds__(256)
snn_mega(const float2* __restrict__ x2,   // [T, B] pairs (x0, x1)
         const float2* __restrict__ w1p,  // [H] pairs
         const float*  __restrict__ w2,   // [2, 256]
         float* __restrict__ out)         // [B, 2]
{
    __shared__ float2 sx[T_STEPS][TILE_B];            // 16KB raw x
    __shared__ unsigned short spool[TILE_B * H_DIM];  // 8KB candidates->survivors
    __shared__ float2 sw1[H_DIM];                     // 2KB
    __shared__ float  sw20[H_DIM], sw21[H_DIM];       // 2KB
    __shared__ float  sR2[H_DIM];                     // 1KB |w|^2
    __shared__ float2 sEnd[16][TILE_B];               // 2KB segment end sums
    __shared__ float2 sVw[NWIN][TILE_B];              // 1.25KB window v values
    __shared__ float  sThr2[TILE_B];                  // TH2 / Vmax^2 per bl
    __shared__ int    sCnt[TILE_B], sOff[TILE_B + 1];
    __shared__ int    wCnt[8], wBase[8], sM;
    __shared__ float  sAcc[TILE_B][2];

    const int tid  = threadIdx.x;
    const int lane = tid & 31, wrp = tid >> 5;
    const int b0   = blockIdx.x * TILE_B;

    // ---- tables (plain loads; R^2 instead of sqrt/atan2) ----
    {
        float2 w = w1p[tid];
        sw1[tid]  = w;
        sR2[tid]  = fmaf(w.x, w.x, w.y * w.y);
        sw20[tid] = w2[tid];
        sw21[tid] = w2[H_DIM + tid];
    }
    if (tid < TILE_B * 2) ((float*)sAcc)[tid] = 0.f;

    // ---- phase A: stage x (coalesced per t-row) ----
    #pragma unroll
    for (int i = 0; i < 8; ++i) {
        int idx = tid + i * 256;
        int t = idx >> 4, bl = idx & 15;
        sx[t][bl] = x2[(size_t)t * B_TOT + b0 + bl];
    }
    __syncthreads();

    // ---- phase B1: segmented scan local sums (thread = (segment j, bl)) ----
    {
        const int j = tid >> 4, bl = tid & 15;
        float A = 0.f, Bv = 0.f;
        #pragma unroll
        for (int i = 0; i < 8; ++i) {
            float2 xv = sx[8 * j + i][bl];
            A  = fmaf(A,  BETA, xv.x);
            Bv = fmaf(Bv, BETA, xv.y);
        }
        sEnd[j][bl] = make_float2(A, Bv);
    }
    __syncthreads();

    // ---- phase B2: window segments reconstruct v_t, t in [118,128) ----
    {
        const int j = tid >> 4, bl = tid & 15;
        if (j >= 14) {
            float VA = 0.f, VB = 0.f;                 // v_{8j-1}
            for (int i = 0; i < j; ++i) {
                float2 e = sEnd[i][bl];
                float p = c_pow8[j - 1 - i];
                VA = fmaf(e.x, p, VA);
                VB = fmaf(e.y, p, VB);
            }
            #pragma unroll
            for (int i = 0; i < 8; ++i) {
                float2 xv = sx[8 * j + i][bl];
                VA = fmaf(VA, BETA, xv.x);
                VB = fmaf(VB, BETA, xv.y);
                int t = 8 * j + i;
                if (t >= WIN0) sVw[t - WIN0][bl] = make_float2(VA, VB);
            }
        }
    }
    __syncthreads();

    // ---- window max |v|^2 -> per-bl R^2 threshold ----
    if (tid < TILE_B) {
        float vm = 0.f;
        #pragma unroll
        for (int k = 0; k < NWIN; ++k) {
            float2 v = sVw[k][tid];
            vm = fmaxf(vm, fmaf(v.x, v.x, v.y * v.y));
        }
        sThr2[tid] = TH2_LO / fmaxf(vm, 1e-30f);
    }
    __syncthreads();

    // ---- phase C1a: CHEAP candidate test (warp w -> bl = w, w+8) ----
    unsigned predbits[2] = {0u, 0u};
    #pragma unroll
    for (int r = 0; r < 2; ++r) {
        const int bl = wrp + r * 8;
        const float th2 = sThr2[bl];
        int cnt = 0;
        #pragma unroll
        for (int c = 0; c < 8; ++c) {
            const int h = c * 32 + lane;
            bool pred = (sR2[h] >= th2);
            if (pred) predbits[r] |= (1u << c);
            cnt += __popc(__ballot_sync(0xffffffffu, pred));
        }
        if (lane == 0) sCnt[bl] = cnt;
    }
    __syncthreads();
    if (tid == 0) {
        int s = 0;
        #pragma unroll
        for (int i = 0; i < TILE_B; ++i) { sOff[i] = s; s += sCnt[i]; }
        sOff[TILE_B] = s;
        sM = 0;
    }
    __syncthreads();

    // ---- scatter candidates into spool (deterministic, bl-sorted) ----
    #pragma unroll
    for (int r = 0; r < 2; ++r) {
        const int bl = wrp + r * 8;
        int base = sOff[bl];
        #pragma unroll
        for (int c = 0; c < 8; ++c) {
            bool pred = (predbits[r] >> c) & 1u;
            unsigned mask = __ballot_sync(0xffffffffu, pred);
            if (pred) {
                int pos = base + __popc(mask & ((1u << lane) - 1u));
                spool[pos] = (unsigned short)((bl << 8) | (c * 32 + lane));
            }
            base += __popc(mask);
        }
    }
    __syncthreads();

    // ---- phase C1b: EXACT test, IN-PLACE compaction within spool ----
    // Reads of batch k happen before its writes; write front sM never
    // exceeds base+256, so batch k+1's reads (>= base+256) are untouched.
    const int P1 = sOff[TILE_B];
    for (int base = 0; base < P1; base += 256) {
        const int i = base + tid;
        const bool act = i < P1;
        const unsigned e = spool[act ? i : 0];     // read first
        const int bl = e >> 8, h = e & 255;
        const float2 w = sw1[h];
        float bmax = -1e30f;
        #pragma unroll
        for (int k = 0; k < NWIN; ++k) {
            float2 v = sVw[k][bl];
            bmax = fmaxf(bmax, fmaf(v.x, w.x, v.y * w.y));
        }
        bool pred = act && (bmax >= TH_LO);
        unsigned mask = __ballot_sync(0xffffffffu, pred);
        if (lane == 0) wCnt[wrp] = __popc(mask);
        __syncthreads();                           // reads done + wCnt visible
        if (tid == 0) {
            int s = sM;
            #pragma unroll
            for (int wv = 0; wv < 8; ++wv) { wBase[wv] = s; s += wCnt[wv]; }
            sM = s;
        }
        __syncthreads();
        if (pred) {
            int pos = wBase[wrp] + __popc(mask & ((1u << lane) - 1u));
            spool[pos] = (unsigned short)e;
        }
    }
    __syncthreads();

    // ---- phase D: pooled exact LIF scan (64 entries per warp-pass) ----
    const int M = sM;
    const u64 BETA2 = 0x3F6666663F666666ULL;
    const u64 NEG12 = 0xBF800000BF800000ULL;

    for (int s0 = wrp * 64; s0 < M; s0 += 8 * 64) {
        const int ia = s0 + lane, ib = s0 + 32 + lane;
        const bool acta = ia < M, actb = ib < M;
        const unsigned ea = spool[acta ? ia : 0];
        const unsigned eb = spool[actb ? ib : 0];
        const int bla = ea >> 8, ha = ea & 255;
        const int blb = eb >> 8, hb = eb & 255;
        const float2 wa = sw1[ha], wb = sw1[hb];
        const u64 w0p = pk2(wa.x, wb.x);
        const u64 w1q = pk2(wa.y, wb.y);

        u64 m = 0, cnt = 0;
        #pragma unroll 4
        for (int t = 0; t < WIN0; ++t) {
            float2 xa = sx[t][bla];
            float2 xb = sx[t][blb];
            u64 qx = pk2(xa.x, xb.x);
            u64 qy = pk2(xa.y, xb.y);
            u64 s = gt1_2(m);                       // reset from prev mem
            m = fma2(m, BETA2, fma2(qx, w0p, mul2(qy, w1q)));
            m = fma2(s, NEG12, m);
        }
        #pragma unroll
        for (int t = WIN0; t < T_STEPS; ++t) {
            float2 xa = sx[t][bla];
            float2 xb = sx[t][blb];
            u64 qx = pk2(xa.x, xb.x);
            u64 qy = pk2(xa.y, xb.y);
            u64 s = gt1_2(m);
            m = fma2(m, BETA2, fma2(qx, w0p, mul2(qy, w1q)));
            m = fma2(s, NEG12, m);
            cnt = add2(cnt, gt1_2(m));              // spk_t, t in [118,127]
        }

        float ca, cb;
        unpk2(cnt, ca, cb);
        if (acta && ca != 0.f) {
            atomicAdd(&sAcc[bla][0], ca * sw20[ha]);
            atomicAdd(&sAcc[bla][1], ca * sw21[ha]);
        }
        if (actb && cb != 0.f) {
            atomicAdd(&sAcc[blb][0], cb * sw20[hb]);
            atomicAdd(&sAcc[blb][1], cb * sw21[hb]);
        }
    }
    __syncthreads();

    // ---- output: exclusive plain stores ----
    if (tid < TILE_B * 2) {
        int bl = tid >> 1, o = tid & 1;
        out[(b0 + bl) * 2 + o] = 0.1f * sAcc[bl][o];
    }
}

extern "C" void kernel_launch(void* const* d_in, const int* in_sizes, int n_in,
                              void* d_out, int out_size) {
    const float2* x  = (const float2*)d_in[0];   // [128, 8192, 2] f32
    const float2* W1 = (const float2*)d_in[1];   // [256, 2] f32
    const float*  W2 = (const float*)d_in[2];    // [2, 256] f32
    float* out = (float*)d_out;                  // [8192, 2] f32

    snn_mega<<<B_TOT / TILE_B, 256>>>(x, W1, W2, out);
}